// round 15
// baseline (speedup 1.0000x reference)
#include <cuda_runtime.h>

// ypred: [B=8, L=32, J=128, N=512] fp32 -> d_in[0]
// xyz:   [B=8, L=32, N=512, 3]     fp32 -> d_in[1]
// out:   scalar fp32 mean
#define NPTS 512
#define JDIM 128
#define JCHUNK 32
#define NCHUNK 4
#define TSTRIDE 513          // odd stride => conflict-free column reads
#define NBL 256

__device__ double g_partials[NBL];
__device__ unsigned int g_ticket = 0;

// ---- packed f32x2 helpers (sm_100+) ----
__device__ __forceinline__ unsigned long long pack2(float lo, float hi) {
    unsigned long long r;
    asm("mov.b64 %0, {%1, %2};" : "=l"(r) : "f"(lo), "f"(hi));
    return r;
}
__device__ __forceinline__ void unpack2(unsigned long long v, float& lo, float& hi) {
    asm("mov.b64 {%0, %1}, %2;" : "=f"(lo), "=f"(hi) : "l"(v));
}
__device__ __forceinline__ unsigned long long mul2(unsigned long long a, unsigned long long b) {
    unsigned long long d;
    asm("mul.rn.f32x2 %0, %1, %2;" : "=l"(d) : "l"(a), "l"(b));
    return d;
}
__device__ __forceinline__ unsigned long long fma2(unsigned long long a, unsigned long long b,
                                                   unsigned long long c) {
    unsigned long long d;
    asm("fma.rn.f32x2 %0, %1, %2, %3;" : "=l"(d) : "l"(a), "l"(b), "l"(c));
    return d;
}

// v-pair for one row against point-pair (a=(x0x1,y0y1), b=(z0z1,sq0sq1))
__device__ __forceinline__ float2 pairv(ulonglong2 a, ulonglong2 b,
                                        unsigned long long x2,
                                        unsigned long long y2,
                                        unsigned long long z2,
                                        unsigned long long c2) {
    unsigned long long dot = mul2(x2, a.x);
    dot = fma2(y2, a.y, dot);
    dot = fma2(z2, b.x, dot);
    unsigned long long val = fma2(dot, c2, b.y);   // v = sq_m - 2*dot
    float2 r;
    unpack2(val, r.x, r.y);
    return r;
}

__device__ __forceinline__ float max8(const float* v) {
    return fmaxf(fmaxf(fmaxf(v[0], v[1]), fmaxf(v[2], v[3])),
                 fmaxf(fmaxf(v[4], v[5]), fmaxf(v[6], v[7])));
}
__device__ __forceinline__ float min8(const float* v) {
    return fminf(fminf(fminf(v[0], v[1]), fminf(v[2], v[3])),
                 fminf(fminf(v[4], v[5]), fminf(v[6], v[7])));
}
__device__ __forceinline__ float min8m(const float* v, float negsq, float INF) {
    float u[8];
    #pragma unroll
    for (int q = 0; q < 8; ++q) u[q] = (v[q] > negsq) ? v[q] : INF;
    return min8(u);
}

__device__ __forceinline__ int rescan_max(const ulonglong2* A, const ulonglong2* B,
                                          unsigned long long x2, unsigned long long y2,
                                          unsigned long long z2, unsigned long long c2,
                                          int pb, float best) {
    int idx = 2 * pb;
    bool found = false;
    #pragma unroll
    for (int p = 0; p < 4; ++p) {
        float2 v = pairv(A[pb + p], B[pb + p], x2, y2, z2, c2);
        if (!found && v.x == best) { idx = 2 * (pb + p);     found = true; }
        if (!found && v.y == best) { idx = 2 * (pb + p) + 1; found = true; }
    }
    return idx;
}
__device__ __forceinline__ int rescan_min(const ulonglong2* A, const ulonglong2* B,
                                          unsigned long long x2, unsigned long long y2,
                                          unsigned long long z2, unsigned long long c2,
                                          int pb, float best, bool masked, float negsq,
                                          float INF) {
    int idx = 2 * pb;
    bool found = false;
    #pragma unroll
    for (int p = 0; p < 4; ++p) {
        float2 v = pairv(A[pb + p], B[pb + p], x2, y2, z2, c2);
        float u0 = (masked && !(v.x > negsq)) ? INF : v.x;
        float u1 = (masked && !(v.y > negsq)) ? INF : v.y;
        if (!found && u0 == best) { idx = 2 * (pb + p);     found = true; }
        if (!found && u1 == best) { idx = 2 * (pb + p) + 1; found = true; }
    }
    return idx;
}

// evaluate one group (4 pairs) for both rows into v0/v1
__device__ __forceinline__ void group_eval(
    const ulonglong2* __restrict__ A, const ulonglong2* __restrict__ B, int pb,
    unsigned long long x20, unsigned long long y20, unsigned long long z20,
    unsigned long long x21, unsigned long long y21, unsigned long long z21,
    unsigned long long c2, float* v0, float* v1) {
    #pragma unroll
    for (int p = 0; p < 4; ++p) {
        ulonglong2 a = A[pb + p];
        ulonglong2 b = B[pb + p];
        float2 r0 = pairv(a, b, x20, y20, z20, c2);
        float2 r1 = pairv(a, b, x21, y21, z21, c2);
        v0[2 * p] = r0.x; v0[2 * p + 1] = r0.y;
        v1[2 * p] = r1.x; v1[2 * p + 1] = r1.y;
    }
}

// 32 x 4B cp.async: one 32x512 ypred chunk into the stride-513 tile
__device__ __forceinline__ void prefetch_chunk(float* buf, const float* src, int tid) {
    unsigned db = (unsigned)__cvta_generic_to_shared(buf);
    #pragma unroll
    for (int r = 0; r < JCHUNK; ++r) {
        const float* s = src + r * NPTS + tid;
        unsigned d = db + (unsigned)((r * TSTRIDE + tid) * 4);
        asm volatile("cp.async.ca.shared.global [%0], [%1], 4;" :: "r"(d), "l"(s));
    }
    asm volatile("cp.async.commit_group;" ::: "memory");
}

__global__ __launch_bounds__(512, 2)
void cll_fused_kernel(const float* __restrict__ ypred,
                      const float* __restrict__ xyz,
                      float* __restrict__ out) {
    __shared__ float4 pA[NPTS / 2];      // (x0,x1,y0,y1) per point pair
    __shared__ float4 pB[NPTS / 2];      // (z0,z1,sq0,sq1)
    __shared__ __align__(16) int sidx[NPTS];  // packed (imax | imin<<16), 8B-aligned for LDS.64
    __shared__ float  mMx[NPTS];         // half-1 publish buffers
    __shared__ int    miMx[NPTS];
    __shared__ float  mMn[NPTS];
    __shared__ int    miMn[NPTS];
    __shared__ double redbuf[256];
    __shared__ int    amLast;
    __shared__ float  tile[JCHUNK * TSTRIDE];

    const int bl  = blockIdx.x;
    const int tid = threadIdx.x;
    const int w   = tid >> 5;
    const int l   = tid & 31;
    const float INF = __int_as_float(0x7f800000);

    const float* yb = ypred + (size_t)bl * (JDIM * NPTS);

    // ---- prefetch ypred chunk 0 under phase 1 ----
    prefetch_chunk(tile, yb, tid);

    // ---- load xyz, squared norms (fixed fma order => diag v == -sq exact) ----
    {
        const float* xb = xyz + (size_t)bl * NPTS * 3;
        float x = xb[tid * 3 + 0];
        float y = xb[tid * 3 + 1];
        float z = xb[tid * 3 + 2];
        float sq = fmaf(z, z, fmaf(y, y, x * x));
        float* fA = (float*)pA;
        float* fB = (float*)pB;
        int base = (tid >> 1) * 4 + (tid & 1);
        fA[base + 0] = x;
        fA[base + 2] = y;
        fB[base + 0] = z;
        fB[base + 2] = sq;
    }
    __syncthreads();

    // ---- phase 1: thread (u,h) scans candidate half h for rows u and u+256 ----
    const int u = tid & 255;
    const int h = tid >> 8;                 // warp-uniform
    const int wdiag = u >> 5;               // warp-uniform masked-group window

    const float* fA = (const float*)pA;
    const float* fB = (const float*)pB;
    const ulonglong2* A = (const ulonglong2*)pA;
    const ulonglong2* B = (const ulonglong2*)pB;

    unsigned long long x20, y20, z20, x21, y21, z21;
    float negsq0, negsq1;
    {
        int b0 = (u >> 1) * 4 + (u & 1);
        float x0 = fA[b0], y0 = fA[b0 + 2], z0 = fB[b0], s0 = fB[b0 + 2];
        float x1 = fA[b0 + 512], y1 = fA[b0 + 514], z1 = fB[b0 + 512], s1 = fB[b0 + 514];
        x20 = pack2(x0, x0); y20 = pack2(y0, y0); z20 = pack2(z0, z0); negsq0 = -s0;
        x21 = pack2(x1, x1); y21 = pack2(y1, y1); z21 = pack2(z1, z1); negsq1 = -s1;
    }
    const unsigned long long c2 = pack2(-2.0f, -2.0f);
    const int pbase = h << 7;

    float bx0 = -INF, bx1 = -INF, bn0 = INF, bn1 = INF;
    int gx0 = 0, gx1 = 0, gn0 = 0, gn1 = 0;

    // segmented group loop: [0,w0) plain | [w0,w0+4) masked | [w0+4,32) plain
    // (bounds are warp-uniform: wdiag = u>>5 identical across the warp)
    const int w0 = wdiag << 2;

    #pragma unroll 2
    for (int g = 0; g < w0; ++g) {
        float v0[8], v1[8];
        group_eval(A, B, pbase + (g << 2), x20, y20, z20, x21, y21, z21, c2, v0, v1);
        float gm0 = max8(v0);
        if (gm0 > bx0) { bx0 = gm0; gx0 = g; }
        float gm1 = max8(v1);
        if (gm1 > bx1) { bx1 = gm1; gx1 = g; }
        float q0 = min8(v0);
        if (q0 < bn0) { bn0 = q0; gn0 = g; }
        float q1 = min8(v1);
        if (q1 < bn1) { bn1 = q1; gn1 = g; }
    }
    #pragma unroll
    for (int k = 0; k < 4; ++k) {
        const int g = w0 + k;
        float v0[8], v1[8];
        group_eval(A, B, pbase + (g << 2), x20, y20, z20, x21, y21, z21, c2, v0, v1);
        float gm0 = max8(v0);
        if (gm0 > bx0) { bx0 = gm0; gx0 = g; }
        float gm1 = max8(v1);
        if (gm1 > bx1) { bx1 = gm1; gx1 = g; }
        // masked row = u+256h: row0 masked iff h==0, row1 iff h==1 (h uniform)
        float q0 = h ? min8(v0) : min8m(v0, negsq0, INF);
        if (q0 < bn0) { bn0 = q0; gn0 = g; }
        float q1 = h ? min8m(v1, negsq1, INF) : min8(v1);
        if (q1 < bn1) { bn1 = q1; gn1 = g; }
    }
    #pragma unroll 2
    for (int g = w0 + 4; g < 32; ++g) {
        float v0[8], v1[8];
        group_eval(A, B, pbase + (g << 2), x20, y20, z20, x21, y21, z21, c2, v0, v1);
        float gm0 = max8(v0);
        if (gm0 > bx0) { bx0 = gm0; gx0 = g; }
        float gm1 = max8(v1);
        if (gm1 > bx1) { bx1 = gm1; gx1 = g; }
        float q0 = min8(v0);
        if (q0 < bn0) { bn0 = q0; gn0 = g; }
        float q1 = min8(v1);
        if (q1 < bn1) { bn1 = q1; gn1 = g; }
    }

    // ---- O(1) exact first-occurrence epilogue on winning groups ----
    int ix0 = rescan_max(A, B, x20, y20, z20, c2, pbase + (gx0 << 2), bx0);
    int ix1 = rescan_max(A, B, x21, y21, z21, c2, pbase + (gx1 << 2), bx1);
    bool m0 = (h == 0) && ((gn0 >> 2) == wdiag);
    bool m1 = (h == 1) && ((gn1 >> 2) == wdiag);
    int in0 = rescan_min(A, B, x20, y20, z20, c2, pbase + (gn0 << 2), bn0, m0, negsq0, INF);
    int in1 = rescan_min(A, B, x21, y21, z21, c2, pbase + (gn1 << 2), bn1, m1, negsq1, INF);

    // ---- merge halves (ties keep half 0 = lower candidate indices) ----
    if (h) {
        mMx[u] = bx0;        miMx[u] = ix0;
        mMn[u] = bn0;        miMn[u] = in0;
        mMx[u + 256] = bx1;  miMx[u + 256] = ix1;
        mMn[u + 256] = bn1;  miMn[u + 256] = in1;
    }
    __syncthreads();
    if (!h) {
        if (mMx[u] > bx0) ix0 = miMx[u];
        if (mMn[u] < bn0) in0 = miMn[u];
        sidx[u] = ix0 | (in0 << 16);
        if (mMx[u + 256] > bx1) ix1 = miMx[u + 256];
        if (mMn[u + 256] < bn1) in1 = miMn[u + 256];
        sidx[u + 256] = ix1 | (in1 << 16);
    }

    // ---- phase 2: conflict-free gathered dots; LDS.64 index loads ----
    asm volatile("cp.async.wait_group 0;" ::: "memory");
    __syncthreads();   // chunk 0 ready; sidx published; table readers done

    float accE = 0.0f, accO = 0.0f;          // dual accumulators: 2x chain ILP
    const float* tl = tile + l * TSTRIDE;    // lane l owns j-row l
    const float* ta = tl + (w << 5);         // this warp's target columns
    const unsigned long long* swp =
        (const unsigned long long*)(sidx + (w << 5));  // 128B offset: 8B aligned

    #pragma unroll 1
    for (int c = 0; c < NCHUNK; ++c) {
        #pragma unroll
        for (int i2 = 0; i2 < 16; ++i2) {
            unsigned long long pk2 = swp[i2];          // two packed idx pairs
            unsigned pkl = (unsigned)pk2;
            unsigned pkh = (unsigned)(pk2 >> 32);
            int mt0 = pkl & 0xffff, nt0 = pkl >> 16;
            int mt1 = pkh & 0xffff, nt1 = pkh >> 16;
            float a0 = ta[2 * i2];       // conflict-free stream reads
            float a1 = ta[2 * i2 + 1];
            accE = fmaf(a0, tl[mt0] - tl[nt0], accE);  // gathers conflict-free
            accO = fmaf(a1, tl[mt1] - tl[nt1], accO);
        }
        if (c + 1 < NCHUNK) {
            __syncthreads();     // everyone done reading chunk c
            prefetch_chunk(tile, yb + (size_t)(c + 1) * (JCHUNK * NPTS), tid);
            asm volatile("cp.async.wait_group 0;" ::: "memory");
            __syncthreads();     // chunk c+1 visible
        }
    }

    // ---- deterministic reduction: warp butterfly + fixed-order sums ----
    double d = (double)accE + (double)accO;
    #pragma unroll
    for (int off = 16; off > 0; off >>= 1)
        d += __shfl_xor_sync(0xffffffffu, d, off);
    if (l == 0) redbuf[w] = d;
    __syncthreads();

    if (tid == 0) {
        double s = 0.0;
        #pragma unroll
        for (int i = 0; i < 16; ++i) s += redbuf[i];
        g_partials[bl] = s;
        __threadfence();
        unsigned t = atomicAdd(&g_ticket, 1u);
        amLast = (t == NBL - 1) ? 1 : 0;
    }
    __syncthreads();

    // ---- fused finalize: last block sums partials in fixed order ----
    if (amLast) {
        if (tid < NBL) redbuf[tid] = ((const volatile double*)g_partials)[tid];
        __syncthreads();
        #pragma unroll
        for (int s2 = NBL / 2; s2 > 0; s2 >>= 1) {
            if (tid < s2) redbuf[tid] += redbuf[tid + s2];
            __syncthreads();
        }
        if (tid == 0) {
            out[0] = (float)(redbuf[0] / (double)((size_t)NBL * NPTS));
            g_ticket = 0;   // reset for next graph replay
        }
    }
}

extern "C" void kernel_launch(void* const* d_in, const int* in_sizes, int n_in,
                              void* d_out, int out_size) {
    const float* ypred = (const float*)d_in[0];
    const float* xyz   = (const float*)d_in[1];
    float* out = (float*)d_out;
    cll_fused_kernel<<<NBL, 512>>>(ypred, xyz, out);
}